// round 5
// baseline (speedup 1.0000x reference)
#include <cuda_runtime.h>
#include <cuda_bf16.h>

// ---------------------------------------------------------------------------
// LSTM_net: 2-layer LSTM (B=256,T=512,I=64,H=256) + MLP head.
//   K1 gemm_xg:  xg = A @ W_ihT + (b_ih+b_hh)  tf32 mma, 128x64 CTA tile,
//       paired LDS.64 reads, double-buffered SMEM, register prefetch.
//   K2 lstm_layer: persistent 128-CTA kernel; 8 batch-groups(32) x 16 slices.
//       W_hh slice resident in SMEM. Flag-array barrier (no atomics):
//       arrive = release-store of own flag, wait = 16-lane poll + ballot.
//   K3 head: tiny MLP.
// ---------------------------------------------------------------------------

#define BATCH  256
#define SEQ    512
#define INP    64
#define HID    256
#define GATE4  1024
#define NGROUP 8        // batch groups of 32
#define GROWS  32       // batch rows per group
#define NSLICE 16       // gate-column slices (16 j-cols x 4 gates = 64 rows of W_hh)

// Scratch (static device globals; allocation-free per harness rules)
__device__ float    g_xg  [(size_t)BATCH * SEQ * GATE4];
__device__ float    g_hseq[(size_t)BATCH * SEQ * HID];
__device__ float    g_hbuf[2 * BATCH * HID];          // ping-pong h (512 KB, L2-resident)
__device__ unsigned g_flag[NGROUP][16];               // per-slice step flags (64B/group)

// ---------------- tf32 helpers ----------------
__device__ __forceinline__ unsigned f2tf(float f) {
    unsigned u;
    asm("cvt.rna.tf32.f32 %0, %1;" : "=r"(u) : "f"(f));
    return u;
}

__device__ __forceinline__ void mma_tf32(float d[4],
                                         unsigned a0, unsigned a1, unsigned a2, unsigned a3,
                                         unsigned b0, unsigned b1) {
    asm volatile(
        "mma.sync.aligned.m16n8k8.row.col.f32.tf32.tf32.f32 "
        "{%0,%1,%2,%3}, {%4,%5,%6,%7}, {%8,%9}, {%0,%1,%2,%3};"
        : "+f"(d[0]), "+f"(d[1]), "+f"(d[2]), "+f"(d[3])
        : "r"(a0), "r"(a1), "r"(a2), "r"(a3), "r"(b0), "r"(b1));
}

__device__ __forceinline__ float sigf(float x) {
    return 1.0f / (1.0f + __expf(-x));
}
__device__ __forceinline__ float tanh_fast(float x) {
    return 2.0f * sigf(2.0f * x) - 1.0f;   // saturation-safe, ~1e-6 abs err
}

// ---------------- release/acquire primitives ----------------
__device__ __forceinline__ void st_release(unsigned* p, unsigned v) {
    asm volatile("st.release.gpu.u32 [%0], %1;" :: "l"(p), "r"(v) : "memory");
}
__device__ __forceinline__ unsigned ld_acquire(const unsigned* p) {
    unsigned v;
    asm volatile("ld.global.acquire.gpu.u32 %0, [%1];"
                 : "=r"(v) : "l"(p) : "memory");
    return v;
}

// ---------------------------------------------------------------------------
// K0: zero the per-slice flags (run before each lstm launch)
// ---------------------------------------------------------------------------
__global__ void reset_sync_kernel() {
    if (threadIdx.x < NGROUP * 16)
        ((unsigned*)g_flag)[threadIdx.x] = 0u;
}

// ---------------------------------------------------------------------------
// K1 v2: C[M,1024] = A[M,K] @ W[1024,K]^T + (bih+bhh)   (tf32)
// CTA tile 128(m) x 64(n), BK=32. 8 warps = 4(m) x 2(n), warp tile 32x32.
// Natural SMEM layout; LDS.64 pairs read logical k (2tg, 2tg+1) for BOTH
// A and B (consistent k-permutation -> dot product unchanged).
// Double-buffered SMEM, register prefetch of next k-tile, 1 bar/iter.
// ---------------------------------------------------------------------------
#define AST  40                        // row stride (words); 40 % 32 == 8
#define BST  40
#define TBUF (128 * AST + 64 * BST)    // words per buffer = 7680
#define GEMM_SMEM (2 * TBUF * 4)       // 61440 bytes

__global__ void __launch_bounds__(256, 2) gemm_xg_kernel(
    const float* __restrict__ A, const float* __restrict__ W,
    const float* __restrict__ bih, const float* __restrict__ bhh,
    float* __restrict__ C, int K)
{
    extern __shared__ unsigned gsm[];

    const int tid  = threadIdx.x;
    const int lane = tid & 31;
    const int warp = tid >> 5;
    const int wm   = (warp >> 1) * 32;      // 4 m-warps
    const int wn   = (warp & 1) * 32;       // 2 n-warps
    const int  n0  = blockIdx.x * 64;       // n fast-varying (B reuse in L2)
    const long m0  = (long)blockIdx.y * 128;

    const int lrow = tid >> 3;              // 0..31
    const int lc4  = (tid & 7) * 4;         // 0,4,..,28

    float4 ra[4], rb[2];

    auto loadRegs = [&](int k0) {
        #pragma unroll
        for (int i = 0; i < 4; i++)
            ra[i] = *reinterpret_cast<const float4*>(
                A + (m0 + lrow + 32 * i) * (long)K + k0 + lc4);
        #pragma unroll
        for (int i = 0; i < 2; i++)
            rb[i] = *reinterpret_cast<const float4*>(
                W + (long)(n0 + lrow + 32 * i) * K + k0 + lc4);
    };
    auto storeTile = [&](int buf) {
        unsigned* Ab = gsm + buf * TBUF;
        unsigned* Bb = Ab + 128 * AST;
        #pragma unroll
        for (int i = 0; i < 4; i++) {
            uint4 q = make_uint4(f2tf(ra[i].x), f2tf(ra[i].y), f2tf(ra[i].z), f2tf(ra[i].w));
            *reinterpret_cast<uint4*>(&Ab[(lrow + 32 * i) * AST + lc4]) = q;
        }
        #pragma unroll
        for (int i = 0; i < 2; i++) {
            uint4 q = make_uint4(f2tf(rb[i].x), f2tf(rb[i].y), f2tf(rb[i].z), f2tf(rb[i].w));
            *reinterpret_cast<uint4*>(&Bb[(lrow + 32 * i) * BST + lc4]) = q;
        }
    };

    float d[2][4][4] = {};
    const int gp  = lane >> 2;
    const int tg2 = (lane & 3) * 2;

    auto compute = [&](int buf) {
        const unsigned* Ab = gsm + buf * TBUF;
        const unsigned* Bb = Ab + 128 * AST;
        #pragma unroll
        for (int kf = 0; kf < 4; kf++) {
            const int kb = kf * 8;
            uint2 a[2][2];
            #pragma unroll
            for (int r = 0; r < 2; r++) {
                a[r][0] = *reinterpret_cast<const uint2*>(&Ab[(wm + 16 * r + gp    ) * AST + kb + tg2]);
                a[r][1] = *reinterpret_cast<const uint2*>(&Ab[(wm + 16 * r + gp + 8) * AST + kb + tg2]);
            }
            #pragma unroll
            for (int j = 0; j < 4; j++) {
                uint2 b = *reinterpret_cast<const uint2*>(&Bb[(wn + 8 * j + gp) * BST + kb + tg2]);
                #pragma unroll
                for (int r = 0; r < 2; r++)
                    mma_tf32(d[r][j], a[r][0].x, a[r][1].x, a[r][0].y, a[r][1].y, b.x, b.y);
            }
        }
    };

    loadRegs(0);
    storeTile(0);
    __syncthreads();

    int cur = 0;
    for (int k0 = 0; k0 < K; k0 += 32) {
        const bool more = (k0 + 32) < K;
        if (more) loadRegs(k0 + 32);     // LDG overlaps compute below
        compute(cur);
        if (more) storeTile(cur ^ 1);    // other buffer: no race with compute
        __syncthreads();
        if (more) cur ^= 1;
    }

    // epilogue: bias + store
    #pragma unroll
    for (int r = 0; r < 2; r++) {
        const int row = wm + 16 * r + gp;
        #pragma unroll
        for (int j = 0; j < 4; j++) {
            int c = n0 + wn + 8 * j + tg2;
            float bi0 = bih[c] + bhh[c];
            float bi1 = bih[c + 1] + bhh[c + 1];
            C[(m0 + row    ) * GATE4 + c    ] = d[r][j][0] + bi0;
            C[(m0 + row    ) * GATE4 + c + 1] = d[r][j][1] + bi1;
            C[(m0 + row + 8) * GATE4 + c    ] = d[r][j][2] + bi0;
            C[(m0 + row + 8) * GATE4 + c + 1] = d[r][j][3] + bi1;
        }
    }
}

// ---------------------------------------------------------------------------
// K2: persistent LSTM layer. 128 CTAs = 8 batch-groups x 16 slices.
// Natural SMEM layout; LDS.64 pairs read logical k (2tg, 2tg+1) for both
// Hs and Ws (consistent permutation).
// ---------------------------------------------------------------------------
#define WSTR 264   // words/row; 264 % 32 == 8 -> conflict-free paired LDS.64
#define GSTR 68
#define SMEM_REC ((64 * WSTR + GROWS * WSTR + GROWS * GSTR + GROWS * 16) * 4)

// ARRIVE: bar.sync orders all block stores; thread0 release-stores own flag.
__device__ __forceinline__ void group_arrive(int group, int slice, unsigned val) {
    __syncthreads();
    if (threadIdx.x == 0) st_release(&g_flag[group][slice], val);
}
// WAIT: warp0 lanes 0..15 poll the 16 flags (one coalesced txn/iteration).
__device__ __forceinline__ void group_wait(int group, unsigned target) {
    if (threadIdx.x < 32) {
        bool ok;
        do {
            unsigned v = (threadIdx.x < 16) ? ld_acquire(&g_flag[group][threadIdx.x])
                                            : target;
            ok = ((int)(v - target) >= 0);
        } while (__ballot_sync(0xFFFFFFFFu, ok) != 0xFFFFFFFFu);
    }
    __syncthreads();
}

__global__ void __launch_bounds__(256, 1) lstm_layer_kernel(
    const float* __restrict__ xg, const float* __restrict__ Whh,
    float* __restrict__ hseq, float* __restrict__ hbuf, int store_all)
{
    extern __shared__ unsigned smem[];
    unsigned* Ws = smem;                                  // [64][WSTR]  resident weights
    unsigned* Hs = smem + 64 * WSTR;                      // [32][WSTR]  h_prev (tf32)
    float*    Gs = (float*)(smem + (64 + GROWS) * WSTR);  // [32][GSTR]  gate pre-acts
    float*    Cs = Gs + GROWS * GSTR;                     // [512]       cell state

    const int tid   = threadIdx.x;
    const int lane  = tid & 31;
    const int warp  = tid >> 5;
    const int group = blockIdx.x >> 4;
    const int slice = blockIdx.x & 15;
    const int b0    = group * GROWS;
    const int j0    = slice * 16;
    const int wm    = (warp & 1) * 16;       // 2 m-warps x 4 n-warps
    const int wn    = (warp >> 1) * 16;

    // resident weight slice: local row rl = gate*16+jj  <-  W_hh[gate*256+j0+jj, :]
    for (int e = tid; e < 64 * 256; e += 256) {
        int rl = e >> 8;                           // col == tid for every e
        int gr = (rl >> 4) * 256 + j0 + (rl & 15);
        Ws[rl * WSTR + tid] = f2tf(Whh[gr * 256 + tid]);
    }
    // zero cell state + our slice of hbuf buffer 0
    for (int e = tid; e < GROWS * 16; e += 256) {
        Cs[e] = 0.0f;
        int bl = e >> 4, j = e & 15;
        hbuf[(b0 + bl) * HID + j0 + j] = 0.0f;
    }
    group_arrive(group, slice, 1u);      // h(0) zeroed + published

    // epilogue cell indices for this thread
    const int ebl = tid >> 4;            // 0..15
    const int ej  = tid & 15;

    for (int t = 0; t < SEQ; t++) {
        const float* hsrc = hbuf + (t & 1) * (BATCH * HID);
        float*       hdst = hbuf + ((t + 1) & 1) * (BATCH * HID);

        // prefetch xg for this step (independent of the barrier) - hides DRAM
        float xr[8];
        #pragma unroll
        for (int rr = 0; rr < 2; rr++) {
            int bl = rr * 16 + ebl;
            long xbase = ((long)(b0 + bl) * SEQ + t) * GATE4 + j0 + ej;
            xr[rr * 4 + 0] = __ldg(&xg[xbase      ]);
            xr[rr * 4 + 1] = __ldg(&xg[xbase + 256]);
            xr[rr * 4 + 2] = __ldg(&xg[xbase + 512]);
            xr[rr * 4 + 3] = __ldg(&xg[xbase + 768]);
        }

        // wait: all 16 slices of this group published h(t)
        group_wait(group, (unsigned)(t + 1));

        // reload h_prev for our 32 batch rows; MUST bypass L1 (other SMs wrote it)
        #pragma unroll
        for (int i = 0; i < GROWS; i++)
            Hs[i * WSTR + tid] = f2tf(__ldcg(&hsrc[(b0 + i) * HID + tid]));
        __syncthreads();

        float d[2][4] = {};
        const int gp  = lane >> 2;
        const int tg2 = (lane & 3) * 2;
        #pragma unroll 8
        for (int kf = 0; kf < 32; kf++) {
            const int kb = kf * 8;
            uint2 va = *reinterpret_cast<const uint2*>(&Hs[(wm + gp    ) * WSTR + kb + tg2]);
            uint2 vb = *reinterpret_cast<const uint2*>(&Hs[(wm + gp + 8) * WSTR + kb + tg2]);
            #pragma unroll
            for (int nf = 0; nf < 2; nf++) {
                uint2 vw = *reinterpret_cast<const uint2*>(&Ws[(wn + nf * 8 + gp) * WSTR + kb + tg2]);
                mma_tf32(d[nf], va.x, vb.x, va.y, vb.y, vw.x, vw.y);
            }
        }

        // stage gate pre-activations to SMEM (cross-warp reshuffle)
        {
            const int r = wm + gp;
            #pragma unroll
            for (int nf = 0; nf < 2; nf++) {
                int c = wn + nf * 8 + tg2;
                Gs[ r      * GSTR + c    ] = d[nf][0];
                Gs[ r      * GSTR + c + 1] = d[nf][1];
                Gs[(r + 8) * GSTR + c    ] = d[nf][2];
                Gs[(r + 8) * GSTR + c + 1] = d[nf][3];
            }
        }
        __syncthreads();

        // gate nonlinearity + state update: each thread owns 2 (b,j) cells
        #pragma unroll
        for (int rr = 0; rr < 2; rr++) {
            int bl = rr * 16 + ebl;
            float gi = Gs[bl * GSTR +      ej] + xr[rr * 4 + 0];
            float gf = Gs[bl * GSTR + 16 + ej] + xr[rr * 4 + 1];
            float gg = Gs[bl * GSTR + 32 + ej] + xr[rr * 4 + 2];
            float go = Gs[bl * GSTR + 48 + ej] + xr[rr * 4 + 3];
            float si = sigf(gi), sf = sigf(gf), so = sigf(go);
            float cv = sf * Cs[bl * 16 + ej] + si * tanh_fast(gg);
            Cs[bl * 16 + ej] = cv;
            float hn = so * tanh_fast(cv);
            hdst[(b0 + bl) * HID + j0 + ej] = hn;
            if (store_all || t == SEQ - 1)
                hseq[((long)(b0 + bl) * SEQ + t) * HID + j0 + ej] = hn;
        }
        group_arrive(group, slice, (unsigned)(t + 2));
    }
}

// ---------------------------------------------------------------------------
// K3: head. out[b, :] = tanh(h_last @ W1^T + b1) @ W2^T + b2
// ---------------------------------------------------------------------------
__global__ void __launch_bounds__(128) head_kernel(
    const float* __restrict__ hseq,
    const float* __restrict__ W1, const float* __restrict__ b1,
    const float* __restrict__ W2, const float* __restrict__ b2,
    float* __restrict__ out)
{
    __shared__ float hl[256];
    __shared__ float z[128];
    const int b = blockIdx.x, tid = threadIdx.x;

    for (int i = tid; i < 256; i += 128)
        hl[i] = hseq[((long)b * SEQ + (SEQ - 1)) * HID + i];
    __syncthreads();

    {
        float acc = b1[tid];
        const float* w = W1 + tid * 256;
        #pragma unroll 8
        for (int h = 0; h < 256; h++) acc += hl[h] * w[h];
        z[tid] = tanhf(acc);
    }
    __syncthreads();

    if (tid < 96) {
        float acc = b2[tid];
        const float* w = W2 + tid * 128;
        #pragma unroll 8
        for (int l = 0; l < 128; l++) acc += z[l] * w[l];
        out[b * 96 + tid] = acc;
    }
}

// ---------------------------------------------------------------------------
extern "C" void kernel_launch(void* const* d_in, const int* in_sizes, int n_in,
                              void* d_out, int out_size)
{
    const float* x    = (const float*)d_in[0];
    const float* Wih0 = (const float*)d_in[1];
    const float* Whh0 = (const float*)d_in[2];
    const float* bih0 = (const float*)d_in[3];
    const float* bhh0 = (const float*)d_in[4];
    const float* Wih1 = (const float*)d_in[5];
    const float* Whh1 = (const float*)d_in[6];
    const float* bih1 = (const float*)d_in[7];
    const float* bhh1 = (const float*)d_in[8];
    const float* W1   = (const float*)d_in[9];
    const float* b1   = (const float*)d_in[10];
    const float* W2   = (const float*)d_in[11];
    const float* b2   = (const float*)d_in[12];
    float* out = (float*)d_out;

    float *xg, *hseq, *hbuf;
    cudaGetSymbolAddress((void**)&xg,   g_xg);
    cudaGetSymbolAddress((void**)&hseq, g_hseq);
    cudaGetSymbolAddress((void**)&hbuf, g_hbuf);

    cudaFuncSetAttribute((const void*)lstm_layer_kernel,
                         cudaFuncAttributeMaxDynamicSharedMemorySize, SMEM_REC);
    cudaFuncSetAttribute((const void*)gemm_xg_kernel,
                         cudaFuncAttributeMaxDynamicSharedMemorySize, GEMM_SMEM);

    dim3 gg(GATE4 / 64, (BATCH * SEQ) / 128);   // n fast-varying: reuse in L2

    // layer 0
    gemm_xg_kernel<<<gg, 256, GEMM_SMEM>>>(x, Wih0, bih0, bhh0, xg, INP);
    reset_sync_kernel<<<1, 128>>>();
    lstm_layer_kernel<<<NGROUP * NSLICE, 256, SMEM_REC>>>(xg, Whh0, hseq, hbuf, 1);
    // layer 1
    gemm_xg_kernel<<<gg, 256, GEMM_SMEM>>>(hseq, Wih1, bih1, bhh1, xg, HID);
    reset_sync_kernel<<<1, 128>>>();
    lstm_layer_kernel<<<NGROUP * NSLICE, 256, SMEM_REC>>>(xg, Whh1, hseq, hbuf, 0);
    // head
    head_kernel<<<BATCH, 128>>>(hseq, W1, b1, W2, b2, out);
}

// round 6
// speedup vs baseline: 1.1782x; 1.1782x over previous
#include <cuda_runtime.h>
#include <cuda_bf16.h>

// ---------------------------------------------------------------------------
// LSTM_net: 2-layer LSTM (B=256,T=512,I=64,H=256) + MLP head.
//   K1 gemm_xg:  xg = A @ W_ihT + (b_ih+b_hh)  tf32 mma, 128x64 CTA tile,
//       paired LDS.64 reads, double-buffered SMEM, register prefetch.
//   K2 lstm_layer: persistent 128-CTA kernel; 16 batch-groups(16) x 8 slices.
//       W_hh slice (128 rows) resident in SMEM. h exchanged through L2 as
//       pre-converted tf32 bits. Counter barrier (red.add.release / acquire
//       spin), one counter per group padded to 128B.
//   K3 head: tiny MLP.
// ---------------------------------------------------------------------------

#define BATCH  256
#define SEQ    512
#define INP    64
#define HID    256
#define GATE4  1024
#define NGROUP 16       // batch groups of 16
#define GROWS  16       // batch rows per group
#define NSLICE 8        // gate-column slices (32 j-cols x 4 gates = 128 rows of W_hh)
#define JCOLS  32       // j columns per slice

// Scratch (static device globals; allocation-free per harness rules)
__device__ float    g_xg  [(size_t)BATCH * SEQ * GATE4];
__device__ float    g_hseq[(size_t)BATCH * SEQ * HID];
__device__ unsigned g_hbuf[2 * BATCH * HID];          // ping-pong h, tf32 bits
__device__ unsigned g_cnt [NGROUP * 32];              // counters, 128B apart

// ---------------- tf32 helpers ----------------
__device__ __forceinline__ unsigned f2tf(float f) {
    unsigned u;
    asm("cvt.rna.tf32.f32 %0, %1;" : "=r"(u) : "f"(f));
    return u;
}

__device__ __forceinline__ void mma_tf32(float d[4],
                                         unsigned a0, unsigned a1, unsigned a2, unsigned a3,
                                         unsigned b0, unsigned b1) {
    asm volatile(
        "mma.sync.aligned.m16n8k8.row.col.f32.tf32.tf32.f32 "
        "{%0,%1,%2,%3}, {%4,%5,%6,%7}, {%8,%9}, {%0,%1,%2,%3};"
        : "+f"(d[0]), "+f"(d[1]), "+f"(d[2]), "+f"(d[3])
        : "r"(a0), "r"(a1), "r"(a2), "r"(a3), "r"(b0), "r"(b1));
}

__device__ __forceinline__ float sigf(float x) {
    return 1.0f / (1.0f + __expf(-x));
}
__device__ __forceinline__ float tanh_fast(float x) {
    return 2.0f * sigf(2.0f * x) - 1.0f;   // saturation-safe, ~1e-6 abs err
}

// ---------------- release/acquire sync primitives ----------------
__device__ __forceinline__ void red_add_release(unsigned* p) {
    asm volatile("red.global.add.release.gpu.u32 [%0], %1;"
                 :: "l"(p), "r"(1u) : "memory");
}
__device__ __forceinline__ unsigned ld_acquire(const unsigned* p) {
    unsigned v;
    asm volatile("ld.global.acquire.gpu.u32 %0, [%1];"
                 : "=r"(v) : "l"(p) : "memory");
    return v;
}

// ---------------------------------------------------------------------------
// K0: zero the group counters (run before each lstm launch)
// ---------------------------------------------------------------------------
__global__ void reset_sync_kernel() {
    if (threadIdx.x < NGROUP * 32) g_cnt[threadIdx.x] = 0u;
}

// ---------------------------------------------------------------------------
// K1 v2: C[M,1024] = A[M,K] @ W[1024,K]^T + (bih+bhh)   (tf32)
// CTA tile 128(m) x 64(n), BK=32. 8 warps = 4(m) x 2(n), warp tile 32x32.
// Natural SMEM layout; LDS.64 pairs read logical k (2tg, 2tg+1) for BOTH
// A and B (consistent k-permutation -> dot product unchanged).
// ---------------------------------------------------------------------------
#define AST  40                        // row stride (words); 40 % 32 == 8
#define BST  40
#define TBUF (128 * AST + 64 * BST)    // words per buffer = 7680
#define GEMM_SMEM (2 * TBUF * 4)       // 61440 bytes

__global__ void __launch_bounds__(256, 2) gemm_xg_kernel(
    const float* __restrict__ A, const float* __restrict__ W,
    const float* __restrict__ bih, const float* __restrict__ bhh,
    float* __restrict__ C, int K)
{
    extern __shared__ unsigned gsm[];

    const int tid  = threadIdx.x;
    const int lane = tid & 31;
    const int warp = tid >> 5;
    const int wm   = (warp >> 1) * 32;      // 4 m-warps
    const int wn   = (warp & 1) * 32;       // 2 n-warps
    const int  n0  = blockIdx.x * 64;       // n fast-varying (B reuse in L2)
    const long m0  = (long)blockIdx.y * 128;

    const int lrow = tid >> 3;              // 0..31
    const int lc4  = (tid & 7) * 4;         // 0,4,..,28

    float4 ra[4], rb[2];

    auto loadRegs = [&](int k0) {
        #pragma unroll
        for (int i = 0; i < 4; i++)
            ra[i] = *reinterpret_cast<const float4*>(
                A + (m0 + lrow + 32 * i) * (long)K + k0 + lc4);
        #pragma unroll
        for (int i = 0; i < 2; i++)
            rb[i] = *reinterpret_cast<const float4*>(
                W + (long)(n0 + lrow + 32 * i) * K + k0 + lc4);
    };
    auto storeTile = [&](int buf) {
        unsigned* Ab = gsm + buf * TBUF;
        unsigned* Bb = Ab + 128 * AST;
        #pragma unroll
        for (int i = 0; i < 4; i++) {
            uint4 q = make_uint4(f2tf(ra[i].x), f2tf(ra[i].y), f2tf(ra[i].z), f2tf(ra[i].w));
            *reinterpret_cast<uint4*>(&Ab[(lrow + 32 * i) * AST + lc4]) = q;
        }
        #pragma unroll
        for (int i = 0; i < 2; i++) {
            uint4 q = make_uint4(f2tf(rb[i].x), f2tf(rb[i].y), f2tf(rb[i].z), f2tf(rb[i].w));
            *reinterpret_cast<uint4*>(&Bb[(lrow + 32 * i) * BST + lc4]) = q;
        }
    };

    float d[2][4][4] = {};
    const int gp  = lane >> 2;
    const int tg2 = (lane & 3) * 2;

    auto compute = [&](int buf) {
        const unsigned* Ab = gsm + buf * TBUF;
        const unsigned* Bb = Ab + 128 * AST;
        #pragma unroll
        for (int kf = 0; kf < 4; kf++) {
            const int kb = kf * 8;
            uint2 a[2][2];
            #pragma unroll
            for (int r = 0; r < 2; r++) {
                a[r][0] = *reinterpret_cast<const uint2*>(&Ab[(wm + 16 * r + gp    ) * AST + kb + tg2]);
                a[r][1] = *reinterpret_cast<const uint2*>(&Ab[(wm + 16 * r + gp + 8) * AST + kb + tg2]);
            }
            #pragma unroll
            for (int j = 0; j < 4; j++) {
                uint2 b = *reinterpret_cast<const uint2*>(&Bb[(wn + 8 * j + gp) * BST + kb + tg2]);
                #pragma unroll
                for (int r = 0; r < 2; r++)
                    mma_tf32(d[r][j], a[r][0].x, a[r][1].x, a[r][0].y, a[r][1].y, b.x, b.y);
            }
        }
    };

    loadRegs(0);
    storeTile(0);
    __syncthreads();

    int cur = 0;
    for (int k0 = 0; k0 < K; k0 += 32) {
        const bool more = (k0 + 32) < K;
        if (more) loadRegs(k0 + 32);     // LDG overlaps compute below
        compute(cur);
        if (more) storeTile(cur ^ 1);    // other buffer: no race with compute
        __syncthreads();
        if (more) cur ^= 1;
    }

    // epilogue: bias + store
    #pragma unroll
    for (int r = 0; r < 2; r++) {
        const int row = wm + 16 * r + gp;
        #pragma unroll
        for (int j = 0; j < 4; j++) {
            int c = n0 + wn + 8 * j + tg2;
            float bi0 = bih[c] + bhh[c];
            float bi1 = bih[c + 1] + bhh[c + 1];
            C[(m0 + row    ) * GATE4 + c    ] = d[r][j][0] + bi0;
            C[(m0 + row    ) * GATE4 + c + 1] = d[r][j][1] + bi1;
            C[(m0 + row + 8) * GATE4 + c    ] = d[r][j][2] + bi0;
            C[(m0 + row + 8) * GATE4 + c + 1] = d[r][j][3] + bi1;
        }
    }
}

// ---------------------------------------------------------------------------
// K2: persistent LSTM layer. 128 CTAs = 16 batch-groups x 8 slices.
// CTA: 16 batch rows x 128 gate cols (= 32 j-cols x 4 gates), K=256.
// 8 warps, each n-tile of 16 (one m16 tile).
// ---------------------------------------------------------------------------
#define WSTR 264   // words/row; 264 % 32 == 8 -> conflict-free paired LDS.64
#define GSTR 132   // 128 + 4
#define LROWS 128  // local weight rows (4 gates x 32 j)
#define SMEM_REC ((LROWS * WSTR + GROWS * WSTR + GROWS * GSTR + GROWS * JCOLS) * 4)

// ARRIVE: bar.sync orders all block stores before thread0's release-add.
__device__ __forceinline__ void group_arrive(int group) {
    __syncthreads();
    if (threadIdx.x == 0) red_add_release(&g_cnt[group * 32]);
}
// WAIT: thread0 acquire-spins to target, bar.sync broadcasts visibility.
__device__ __forceinline__ void group_wait(int group, unsigned target) {
    if (threadIdx.x == 0) {
        while ((int)(ld_acquire(&g_cnt[group * 32]) - target) < 0) { }
    }
    __syncthreads();
}

__global__ void __launch_bounds__(256, 1) lstm_layer_kernel(
    const float* __restrict__ xg, const float* __restrict__ Whh,
    float* __restrict__ hseq, unsigned* __restrict__ hbuf, int store_all)
{
    extern __shared__ unsigned smem[];
    unsigned* Ws = smem;                                     // [128][WSTR] weights
    unsigned* Hs = smem + LROWS * WSTR;                      // [16][WSTR]  h_prev (tf32 bits)
    float*    Gs = (float*)(smem + (LROWS + GROWS) * WSTR);  // [16][GSTR]  gate pre-acts
    float*    Cs = Gs + GROWS * GSTR;                        // [16*32]     cell state

    const int tid   = threadIdx.x;
    const int lane  = tid & 31;
    const int warp  = tid >> 5;
    const int group = blockIdx.x >> 3;
    const int slice = blockIdx.x & 7;
    const int b0    = group * GROWS;
    const int j0    = slice * JCOLS;
    const int wn    = warp * 16;          // 8 n-warps, single m16 tile

    // resident weight slice: local row rl = gate*32+jj <- W_hh[gate*256+j0+jj, :]
    for (int e = tid; e < LROWS * 256; e += 256) {
        int rl = e >> 8;                               // col == tid for every e
        int gr = (rl >> 5) * 256 + j0 + (rl & 31);
        Ws[rl * WSTR + tid] = f2tf(Whh[gr * 256 + tid]);
    }
    // zero cell state + our slice of hbuf buffer 0
    for (int e = tid; e < GROWS * JCOLS; e += 256) {
        Cs[e] = 0.0f;
        int bl = e >> 5, j = e & 31;
        hbuf[(b0 + bl) * HID + j0 + j] = 0u;           // tf32 bits of 0.0
    }
    group_arrive(group);        // arrival #1: h(0) zeroed + published

    // epilogue cells: thread owns cells {tid, tid+256} of 16x32=512
    const int ebl0 = tid >> 5;            // 0..7
    const int ej   = tid & 31;

    for (int t = 0; t < SEQ; t++) {
        const unsigned* hsrc = hbuf + (t & 1) * (BATCH * HID);
        unsigned*       hdst = hbuf + ((t + 1) & 1) * (BATCH * HID);

        // prefetch xg for this step (independent of the barrier) - hides DRAM
        float xr[8];
        #pragma unroll
        for (int rr = 0; rr < 2; rr++) {
            int bl = ebl0 + rr * 8;
            long xbase = ((long)(b0 + bl) * SEQ + t) * GATE4 + j0 + ej;
            xr[rr * 4 + 0] = __ldg(&xg[xbase      ]);
            xr[rr * 4 + 1] = __ldg(&xg[xbase + 256]);
            xr[rr * 4 + 2] = __ldg(&xg[xbase + 512]);
            xr[rr * 4 + 3] = __ldg(&xg[xbase + 768]);
        }

        // wait: all 8 slices of this group published h(t)
        group_wait(group, (unsigned)(t + 1) * NSLICE);

        // reload h_prev (tf32 bits, straight copy); bypass L1 (other SMs wrote)
        #pragma unroll
        for (int i = 0; i < GROWS; i++)
            Hs[i * WSTR + tid] = __ldcg(&hsrc[(b0 + i) * HID + tid]);
        __syncthreads();

        float d[2][4] = {};
        const int gp  = lane >> 2;
        const int tg2 = (lane & 3) * 2;
        #pragma unroll 8
        for (int kf = 0; kf < 32; kf++) {
            const int kb = kf * 8;
            uint2 va = *reinterpret_cast<const uint2*>(&Hs[ gp      * WSTR + kb + tg2]);
            uint2 vb = *reinterpret_cast<const uint2*>(&Hs[(gp + 8) * WSTR + kb + tg2]);
            #pragma unroll
            for (int nf = 0; nf < 2; nf++) {
                uint2 vw = *reinterpret_cast<const uint2*>(&Ws[(wn + nf * 8 + gp) * WSTR + kb + tg2]);
                mma_tf32(d[nf], va.x, vb.x, va.y, vb.y, vw.x, vw.y);
            }
        }

        // stage gate pre-activations to SMEM (cross-warp reshuffle)
        {
            #pragma unroll
            for (int nf = 0; nf < 2; nf++) {
                int c = wn + nf * 8 + tg2;
                Gs[ gp      * GSTR + c    ] = d[nf][0];
                Gs[ gp      * GSTR + c + 1] = d[nf][1];
                Gs[(gp + 8) * GSTR + c    ] = d[nf][2];
                Gs[(gp + 8) * GSTR + c + 1] = d[nf][3];
            }
        }
        __syncthreads();

        // gate nonlinearity + state update: 2 (b,j) cells per thread
        #pragma unroll
        for (int rr = 0; rr < 2; rr++) {
            int bl = ebl0 + rr * 8;
            float gi = Gs[bl * GSTR +      ej] + xr[rr * 4 + 0];
            float gf = Gs[bl * GSTR + 32 + ej] + xr[rr * 4 + 1];
            float gg = Gs[bl * GSTR + 64 + ej] + xr[rr * 4 + 2];
            float go = Gs[bl * GSTR + 96 + ej] + xr[rr * 4 + 3];
            float si = sigf(gi), sf = sigf(gf), so = sigf(go);
            float cv = sf * Cs[bl * JCOLS + ej] + si * tanh_fast(gg);
            Cs[bl * JCOLS + ej] = cv;
            float hn = so * tanh_fast(cv);
            hdst[(b0 + bl) * HID + j0 + ej] = f2tf(hn);   // pre-converted tf32
            if (store_all || t == SEQ - 1)
                hseq[((long)(b0 + bl) * SEQ + t) * HID + j0 + ej] = hn;
        }
        group_arrive(group);     // exactly one arrival per CTA per step
    }
}

// ---------------------------------------------------------------------------
// K3: head. out[b, :] = tanh(h_last @ W1^T + b1) @ W2^T + b2
// ---------------------------------------------------------------------------
__global__ void __launch_bounds__(128) head_kernel(
    const float* __restrict__ hseq,
    const float* __restrict__ W1, const float* __restrict__ b1,
    const float* __restrict__ W2, const float* __restrict__ b2,
    float* __restrict__ out)
{
    __shared__ float hl[256];
    __shared__ float z[128];
    const int b = blockIdx.x, tid = threadIdx.x;

    for (int i = tid; i < 256; i += 128)
        hl[i] = hseq[((long)b * SEQ + (SEQ - 1)) * HID + i];
    __syncthreads();

    {
        float acc = b1[tid];
        const float* w = W1 + tid * 256;
        #pragma unroll 8
        for (int h = 0; h < 256; h++) acc += hl[h] * w[h];
        z[tid] = tanhf(acc);
    }
    __syncthreads();

    if (tid < 96) {
        float acc = b2[tid];
        const float* w = W2 + tid * 128;
        #pragma unroll 8
        for (int l = 0; l < 128; l++) acc += z[l] * w[l];
        out[b * 96 + tid] = acc;
    }
}

// ---------------------------------------------------------------------------
extern "C" void kernel_launch(void* const* d_in, const int* in_sizes, int n_in,
                              void* d_out, int out_size)
{
    const float* x    = (const float*)d_in[0];
    const float* Wih0 = (const float*)d_in[1];
    const float* Whh0 = (const float*)d_in[2];
    const float* bih0 = (const float*)d_in[3];
    const float* bhh0 = (const float*)d_in[4];
    const float* Wih1 = (const float*)d_in[5];
    const float* Whh1 = (const float*)d_in[6];
    const float* bih1 = (const float*)d_in[7];
    const float* bhh1 = (const float*)d_in[8];
    const float* W1   = (const float*)d_in[9];
    const float* b1   = (const float*)d_in[10];
    const float* W2   = (const float*)d_in[11];
    const float* b2   = (const float*)d_in[12];
    float* out = (float*)d_out;

    float *xg, *hseq; unsigned *hbuf;
    cudaGetSymbolAddress((void**)&xg,   g_xg);
    cudaGetSymbolAddress((void**)&hseq, g_hseq);
    cudaGetSymbolAddress((void**)&hbuf, g_hbuf);

    cudaFuncSetAttribute((const void*)lstm_layer_kernel,
                         cudaFuncAttributeMaxDynamicSharedMemorySize, SMEM_REC);
    cudaFuncSetAttribute((const void*)gemm_xg_kernel,
                         cudaFuncAttributeMaxDynamicSharedMemorySize, GEMM_SMEM);

    dim3 gg(GATE4 / 64, (BATCH * SEQ) / 128);   // n fast-varying: reuse in L2

    // layer 0
    gemm_xg_kernel<<<gg, 256, GEMM_SMEM>>>(x, Wih0, bih0, bhh0, xg, INP);
    reset_sync_kernel<<<1, NGROUP * 32>>>();
    lstm_layer_kernel<<<NGROUP * NSLICE, 256, SMEM_REC>>>(xg, Whh0, hseq, hbuf, 1);
    // layer 1
    gemm_xg_kernel<<<gg, 256, GEMM_SMEM>>>(hseq, Wih1, bih1, bhh1, xg, HID);
    reset_sync_kernel<<<1, NGROUP * 32>>>();
    lstm_layer_kernel<<<NGROUP * NSLICE, 256, SMEM_REC>>>(xg, Whh1, hseq, hbuf, 0);
    // head
    head_kernel<<<BATCH, 128>>>(hseq, W1, b1, W2, b2, out);
}

// round 7
// speedup vs baseline: 1.3745x; 1.1666x over previous
#include <cuda_runtime.h>
#include <cuda_bf16.h>

// ---------------------------------------------------------------------------
// LSTM_net: 2-layer LSTM (B=256,T=512,I=64,H=256) + MLP head.
//   K1 gemm_xg: tf32 mma, 128x64 CTA tile, quad-permuted SMEM + LDS.128.
//   K2 lstm_layer: persistent 128-CTA kernel; 16 groups(16 rows) x 8 slices.
//       W_hh fragments in REGISTERS (loaded once), h in quad-permuted SMEM
//       read via LDS.128. Counter barrier (red.add.release / acquire spin).
//   K3 head: tiny MLP.
// Quad permutation: within each 16-k block, logical k order
// [e0,e1,o0,o1, e2,e3,o2,o3, ...] (e=first 8, o=second 8) so a lane's
// fragments for a kf-PAIR are 16B-contiguous. Applied identically to both
// mma operands -> results bit-identical to the unpermuted computation.
// ---------------------------------------------------------------------------

#define BATCH  256
#define SEQ    512
#define INP    64
#define HID    256
#define GATE4  1024
#define NGROUP 16       // batch groups of 16
#define GROWS  16       // batch rows per group
#define NSLICE 8        // gate-column slices (32 j-cols x 4 gates = 128 rows)
#define JCOLS  32       // j columns per slice

// Scratch (static device globals; allocation-free per harness rules)
__device__ float    g_xg  [(size_t)BATCH * SEQ * GATE4];
__device__ float    g_hseq[(size_t)BATCH * SEQ * HID];
__device__ unsigned g_hbuf[2 * BATCH * HID];          // ping-pong h, tf32 bits
__device__ unsigned g_cnt [NGROUP * 32];              // counters, 128B apart

// ---------------- tf32 helpers ----------------
__device__ __forceinline__ unsigned f2tf(float f) {
    unsigned u;
    asm("cvt.rna.tf32.f32 %0, %1;" : "=r"(u) : "f"(f));
    return u;
}

__device__ __forceinline__ void mma_tf32(float d[4],
                                         unsigned a0, unsigned a1, unsigned a2, unsigned a3,
                                         unsigned b0, unsigned b1) {
    asm volatile(
        "mma.sync.aligned.m16n8k8.row.col.f32.tf32.tf32.f32 "
        "{%0,%1,%2,%3}, {%4,%5,%6,%7}, {%8,%9}, {%0,%1,%2,%3};"
        : "+f"(d[0]), "+f"(d[1]), "+f"(d[2]), "+f"(d[3])
        : "r"(a0), "r"(a1), "r"(a2), "r"(a3), "r"(b0), "r"(b1));
}

__device__ __forceinline__ float sigf(float x) {
    return 1.0f / (1.0f + __expf(-x));
}
__device__ __forceinline__ float tanh_fast(float x) {
    return 2.0f * sigf(2.0f * x) - 1.0f;
}

// quad permutation within a 16-word block
__device__ __forceinline__ int pquad(int i) {
    return 4 * ((i & 7) >> 1) + 2 * (i >> 3) + (i & 1);
}

// ---------------- release/acquire sync primitives ----------------
__device__ __forceinline__ void red_add_release(unsigned* p) {
    asm volatile("red.global.add.release.gpu.u32 [%0], %1;"
                 :: "l"(p), "r"(1u) : "memory");
}
__device__ __forceinline__ unsigned ld_acquire(const unsigned* p) {
    unsigned v;
    asm volatile("ld.global.acquire.gpu.u32 %0, [%1];"
                 : "=r"(v) : "l"(p) : "memory");
    return v;
}

__global__ void reset_sync_kernel() {
    if (threadIdx.x < NGROUP * 32) g_cnt[threadIdx.x] = 0u;
}

// ---------------------------------------------------------------------------
// K1 v3: C[M,1024] = A[M,K] @ W[1024,K]^T + (bih+bhh)   (tf32)
// CTA 128x64, BK=32, 8 warps = 4(m)x2(n), warp tile 32x32.
// Quad-permuted SMEM (stride 48 = 16 mod 32 -> conflict-free LDS.128).
// ---------------------------------------------------------------------------
#define AST  48
#define TBUF (192 * AST)               // A(128) + B(64) rows
#define GEMM_SMEM (2 * TBUF * 4)       // 73728 bytes

__global__ void __launch_bounds__(256, 2) gemm_xg_kernel(
    const float* __restrict__ A, const float* __restrict__ W,
    const float* __restrict__ bih, const float* __restrict__ bhh,
    float* __restrict__ C, int K)
{
    extern __shared__ unsigned gsm[];

    const int tid  = threadIdx.x;
    const int lane = tid & 31;
    const int warp = tid >> 5;
    const int wm   = (warp >> 1) * 32;      // 4 m-warps
    const int wn   = (warp & 1) * 32;       // 2 n-warps
    const int  n0  = blockIdx.x * 64;       // n fast-varying (B reuse in L2)
    const long m0  = (long)blockIdx.y * 128;

    const int lrow = tid >> 3;              // 0..31
    const int lc4  = (tid & 7) * 4;         // 0,4,..,28

    float4 ra[4], rb[2];

    auto loadRegs = [&](int k0) {
        #pragma unroll
        for (int i = 0; i < 4; i++)
            ra[i] = *reinterpret_cast<const float4*>(
                A + (m0 + lrow + 32 * i) * (long)K + k0 + lc4);
        #pragma unroll
        for (int i = 0; i < 2; i++)
            rb[i] = *reinterpret_cast<const float4*>(
                W + (long)(n0 + lrow + 32 * i) * K + k0 + lc4);
    };
    // quad-permuted store: logical float4 at (row, c4) -> two uint2 at p, p+4
    auto stsquad = [&](unsigned* base, int row, int c4, float4 v) {
        int i = c4 & 15;
        int p = row * AST + ((c4 >> 4) << 4) + 4 * ((i & 7) >> 1) + 2 * (i >> 3);
        *reinterpret_cast<uint2*>(base + p)     = make_uint2(f2tf(v.x), f2tf(v.y));
        *reinterpret_cast<uint2*>(base + p + 4) = make_uint2(f2tf(v.z), f2tf(v.w));
    };
    auto storeTile = [&](int buf) {
        unsigned* Ab = gsm + buf * TBUF;
        unsigned* Bb = Ab + 128 * AST;
        #pragma unroll
        for (int i = 0; i < 4; i++) stsquad(Ab, lrow + 32 * i, lc4, ra[i]);
        #pragma unroll
        for (int i = 0; i < 2; i++) stsquad(Bb, lrow + 32 * i, lc4, rb[i]);
    };

    float d[2][4][4] = {};
    const int gp  = lane >> 2;
    const int tg  = lane & 3;
    const int tg2 = tg * 2;

    auto compute = [&](int buf) {
        const unsigned* Ab = gsm + buf * TBUF;
        const unsigned* Bb = Ab + 128 * AST;
        #pragma unroll
        for (int m = 0; m < 2; m++) {            // two 16-k blocks
            const int kb = m * 16 + 4 * tg;
            uint4 a[2][2];
            #pragma unroll
            for (int r = 0; r < 2; r++) {
                a[r][0] = *reinterpret_cast<const uint4*>(&Ab[(wm + 16 * r + gp    ) * AST + kb]);
                a[r][1] = *reinterpret_cast<const uint4*>(&Ab[(wm + 16 * r + gp + 8) * AST + kb]);
            }
            #pragma unroll
            for (int j = 0; j < 4; j++) {
                uint4 b = *reinterpret_cast<const uint4*>(&Bb[(wn + 8 * j + gp) * AST + kb]);
                #pragma unroll
                for (int r = 0; r < 2; r++) {
                    mma_tf32(d[r][j], a[r][0].x, a[r][1].x, a[r][0].y, a[r][1].y, b.x, b.y);
                    mma_tf32(d[r][j], a[r][0].z, a[r][1].z, a[r][0].w, a[r][1].w, b.z, b.w);
                }
            }
        }
    };

    loadRegs(0);
    storeTile(0);
    __syncthreads();

    int cur = 0;
    for (int k0 = 0; k0 < K; k0 += 32) {
        const bool more = (k0 + 32) < K;
        if (more) loadRegs(k0 + 32);
        compute(cur);
        if (more) storeTile(cur ^ 1);
        __syncthreads();
        if (more) cur ^= 1;
    }

    #pragma unroll
    for (int r = 0; r < 2; r++) {
        const int row = wm + 16 * r + gp;
        #pragma unroll
        for (int j = 0; j < 4; j++) {
            int c = n0 + wn + 8 * j + tg2;
            float bi0 = bih[c] + bhh[c];
            float bi1 = bih[c + 1] + bhh[c + 1];
            C[(m0 + row    ) * GATE4 + c    ] = d[r][j][0] + bi0;
            C[(m0 + row    ) * GATE4 + c + 1] = d[r][j][1] + bi1;
            C[(m0 + row + 8) * GATE4 + c    ] = d[r][j][2] + bi0;
            C[(m0 + row + 8) * GATE4 + c + 1] = d[r][j][3] + bi1;
        }
    }
}

// ---------------------------------------------------------------------------
// K2: persistent LSTM layer. 128 CTAs = 16 batch-groups x 8 slices.
// W fragments in registers; h in quad-permuted SMEM (stride 272).
// ---------------------------------------------------------------------------
#define WSTR 272   // 272 % 32 == 16 -> conflict-free LDS.128
#define GSTR 132
#define SMEM_REC ((GROWS * WSTR + GROWS * GSTR + GROWS * JCOLS) * 4)

__device__ __forceinline__ void group_arrive(int group) {
    __syncthreads();
    if (threadIdx.x == 0) red_add_release(&g_cnt[group * 32]);
}
__device__ __forceinline__ void group_wait(int group, unsigned target) {
    if (threadIdx.x == 0) {
        while ((int)(ld_acquire(&g_cnt[group * 32]) - target) < 0) { }
    }
    __syncthreads();
}

__global__ void __launch_bounds__(256, 1) lstm_layer_kernel(
    const float* __restrict__ xg, const float* __restrict__ Whh,
    float* __restrict__ hseq, unsigned* __restrict__ hbuf, int store_all)
{
    extern __shared__ unsigned smem[];
    unsigned* Hs = smem;                          // [16][WSTR] h_prev (tf32, permuted)
    float*    Gs = (float*)(smem + GROWS * WSTR); // [16][GSTR] gate pre-acts
    float*    Cs = Gs + GROWS * GSTR;             // [16*32]    cell state

    const int tid   = threadIdx.x;
    const int lane  = tid & 31;
    const int warp  = tid >> 5;
    const int group = blockIdx.x >> 3;
    const int slice = blockIdx.x & 7;
    const int b0    = group * GROWS;
    const int j0    = slice * JCOLS;
    const int wn    = warp * 16;          // 8 n-warps, single m16 tile
    const int gp    = lane >> 2;
    const int tg    = lane & 3;
    const int tg2   = tg * 2;

    // ---- load W fragments into registers (once; step-invariant) ----
    // lane supplies mma B-operand for output col gp of each 8-col tile:
    // local row rl = wn + nf*8 + gp -> W_hh row gate*256 + j0 + jj.
    uint4 wreg[16][2];
    #pragma unroll
    for (int m = 0; m < 16; m++) {
        #pragma unroll
        for (int nf = 0; nf < 2; nf++) {
            int rl = wn + nf * 8 + gp;
            int gr = (rl >> 5) * 256 + j0 + (rl & 31);
            const float* wp = Whh + gr * 256 + 16 * m;
            float2 lo = *reinterpret_cast<const float2*>(wp + 2 * tg);      // kf even
            float2 hi = *reinterpret_cast<const float2*>(wp + 8 + 2 * tg);  // kf odd
            wreg[m][nf] = make_uint4(f2tf(lo.x), f2tf(lo.y), f2tf(hi.x), f2tf(hi.y));
        }
    }

    // permuted column for this thread's h element (col == tid)
    const int hcol = ((tid >> 4) << 4) + pquad(tid & 15);

    // zero cell state + our slice of hbuf buffer 0
    for (int e = tid; e < GROWS * JCOLS; e += 256) {
        Cs[e] = 0.0f;
        int bl = e >> 5, j = e & 31;
        hbuf[(b0 + bl) * HID + j0 + j] = 0u;
    }
    group_arrive(group);        // arrival #1: h(0) zeroed + published

    const int ebl0 = tid >> 5;            // 0..7
    const int ej   = tid & 31;

    for (int t = 0; t < SEQ; t++) {
        const unsigned* hsrc = hbuf + (t & 1) * (BATCH * HID);
        unsigned*       hdst = hbuf + ((t + 1) & 1) * (BATCH * HID);

        // prefetch xg for this step (independent of the barrier)
        float xr[8];
        #pragma unroll
        for (int rr = 0; rr < 2; rr++) {
            int bl = ebl0 + rr * 8;
            long xbase = ((long)(b0 + bl) * SEQ + t) * GATE4 + j0 + ej;
            xr[rr * 4 + 0] = __ldg(&xg[xbase      ]);
            xr[rr * 4 + 1] = __ldg(&xg[xbase + 256]);
            xr[rr * 4 + 2] = __ldg(&xg[xbase + 512]);
            xr[rr * 4 + 3] = __ldg(&xg[xbase + 768]);
        }

        group_wait(group, (unsigned)(t + 1) * NSLICE);

        // reload h_prev (tf32 bits) into permuted SMEM; bypass L1
        #pragma unroll
        for (int i = 0; i < GROWS; i++)
            Hs[i * WSTR + hcol] = __ldcg(&hsrc[(b0 + i) * HID + tid]);
        __syncthreads();

        float d[2][4] = {};
        #pragma unroll
        for (int m = 0; m < 16; m++) {
            const int kb = m * 16 + 4 * tg;
            uint4 va = *reinterpret_cast<const uint4*>(&Hs[ gp      * WSTR + kb]);
            uint4 vb = *reinterpret_cast<const uint4*>(&Hs[(gp + 8) * WSTR + kb]);
            #pragma unroll
            for (int nf = 0; nf < 2; nf++) {
                mma_tf32(d[nf], va.x, vb.x, va.y, vb.y, wreg[m][nf].x, wreg[m][nf].y);
                mma_tf32(d[nf], va.z, vb.z, va.w, vb.w, wreg[m][nf].z, wreg[m][nf].w);
            }
        }

        // stage gate pre-activations to SMEM (cross-warp reshuffle)
        #pragma unroll
        for (int nf = 0; nf < 2; nf++) {
            int c = wn + nf * 8 + tg2;
            Gs[ gp      * GSTR + c    ] = d[nf][0];
            Gs[ gp      * GSTR + c + 1] = d[nf][1];
            Gs[(gp + 8) * GSTR + c    ] = d[nf][2];
            Gs[(gp + 8) * GSTR + c + 1] = d[nf][3];
        }
        __syncthreads();

        // gate nonlinearity + state update: 2 (b,j) cells per thread
        #pragma unroll
        for (int rr = 0; rr < 2; rr++) {
            int bl = ebl0 + rr * 8;
            float gi = Gs[bl * GSTR +      ej] + xr[rr * 4 + 0];
            float gf = Gs[bl * GSTR + 32 + ej] + xr[rr * 4 + 1];
            float gg = Gs[bl * GSTR + 64 + ej] + xr[rr * 4 + 2];
            float go = Gs[bl * GSTR + 96 + ej] + xr[rr * 4 + 3];
            float si = sigf(gi), sf = sigf(gf), so = sigf(go);
            float cv = sf * Cs[bl * JCOLS + ej] + si * tanh_fast(gg);
            Cs[bl * JCOLS + ej] = cv;
            float hn = so * tanh_fast(cv);
            hdst[(b0 + bl) * HID + j0 + ej] = f2tf(hn);
            if (store_all || t == SEQ - 1)
                hseq[((long)(b0 + bl) * SEQ + t) * HID + j0 + ej] = hn;
        }
        group_arrive(group);
    }
}

// ---------------------------------------------------------------------------
// K3: head. out[b, :] = tanh(h_last @ W1^T + b1) @ W2^T + b2
// ---------------------------------------------------------------------------
__global__ void __launch_bounds__(128) head_kernel(
    const float* __restrict__ hseq,
    const float* __restrict__ W1, const float* __restrict__ b1,
    const float* __restrict__ W2, const float* __restrict__ b2,
    float* __restrict__ out)
{
    __shared__ float hl[256];
    __shared__ float z[128];
    const int b = blockIdx.x, tid = threadIdx.x;

    for (int i = tid; i < 256; i += 128)
        hl[i] = hseq[((long)b * SEQ + (SEQ - 1)) * HID + i];
    __syncthreads();

    {
        float acc = b1[tid];
        const float* w = W1 + tid * 256;
        #pragma unroll 8
        for (int h = 0; h < 256; h++) acc += hl[h] * w[h];
        z[tid] = tanhf(acc);
    }
    __syncthreads();

    if (tid < 96) {
        float acc = b2[tid];
        const float* w = W2 + tid * 128;
        #pragma unroll 8
        for (int l = 0; l < 128; l++) acc += z[l] * w[l];
        out[b * 96 + tid] = acc;
    }
}

// ---------------------------------------------------------------------------
extern "C" void kernel_launch(void* const* d_in, const int* in_sizes, int n_in,
                              void* d_out, int out_size)
{
    const float* x    = (const float*)d_in[0];
    const float* Wih0 = (const float*)d_in[1];
    const float* Whh0 = (const float*)d_in[2];
    const float* bih0 = (const float*)d_in[3];
    const float* bhh0 = (const float*)d_in[4];
    const float* Wih1 = (const float*)d_in[5];
    const float* Whh1 = (const float*)d_in[6];
    const float* bih1 = (const float*)d_in[7];
    const float* bhh1 = (const float*)d_in[8];
    const float* W1   = (const float*)d_in[9];
    const float* b1   = (const float*)d_in[10];
    const float* W2   = (const float*)d_in[11];
    const float* b2   = (const float*)d_in[12];
    float* out = (float*)d_out;

    float *xg, *hseq; unsigned *hbuf;
    cudaGetSymbolAddress((void**)&xg,   g_xg);
    cudaGetSymbolAddress((void**)&hseq, g_hseq);
    cudaGetSymbolAddress((void**)&hbuf, g_hbuf);

    cudaFuncSetAttribute((const void*)lstm_layer_kernel,
                         cudaFuncAttributeMaxDynamicSharedMemorySize, SMEM_REC);
    cudaFuncSetAttribute((const void*)gemm_xg_kernel,
                         cudaFuncAttributeMaxDynamicSharedMemorySize, GEMM_SMEM);

    dim3 gg(GATE4 / 64, (BATCH * SEQ) / 128);   // n fast-varying: reuse in L2

    // layer 0
    gemm_xg_kernel<<<gg, 256, GEMM_SMEM>>>(x, Wih0, bih0, bhh0, xg, INP);
    reset_sync_kernel<<<1, NGROUP * 32>>>();
    lstm_layer_kernel<<<NGROUP * NSLICE, 256, SMEM_REC>>>(xg, Whh0, hseq, hbuf, 1);
    // layer 1
    gemm_xg_kernel<<<gg, 256, GEMM_SMEM>>>(hseq, Wih1, bih1, bhh1, xg, HID);
    reset_sync_kernel<<<1, NGROUP * 32>>>();
    lstm_layer_kernel<<<NGROUP * NSLICE, 256, SMEM_REC>>>(xg, Whh1, hseq, hbuf, 0);
    // head
    head_kernel<<<BATCH, 128>>>(hseq, W1, b1, W2, b2, out);
}

// round 10
// speedup vs baseline: 1.4055x; 1.0226x over previous
#include <cuda_runtime.h>
#include <cuda_bf16.h>

// ---------------------------------------------------------------------------
// LSTM_net: 2-layer LSTM (B=256,T=512,I=64,H=256) + MLP head.
// All GEMM/LSTM operands pre-converted to tf32 bits in quad-permuted k-layout:
//   within each 16-k block, order [k0,k1,k8,k9, k2,k3,k10,k11, ...] so a
//   lane's mma fragments for a kf-pair are one 16B LDS.128. Permutation is
//   applied to BOTH operands -> dot products (and results) unchanged.
//   K1 gemm_xg: pure cp.async -> LDS.128 -> mma (no CVT in-loop).
//   K2 lstm_layer: persistent 128 CTAs; 16 groups(16 rows) x 8 slices; W_hh
//      in registers; h reload = 4x cp.async.cg 16B/thread (FULL 16KB tile);
//      split mma accumulators for ILP.
//   K3 head: tiny MLP.
// ---------------------------------------------------------------------------

#define BATCH  256
#define SEQ    512
#define INP    64
#define HID    256
#define GATE4  1024
#define NGROUP 16
#define GROWS  16
#define NSLICE 8
#define JCOLS  32

// Scratch (static device globals; allocation-free per harness rules)
__device__ float    g_xg  [(size_t)BATCH * SEQ * GATE4];
__device__ unsigned g_hseq[(size_t)BATCH * SEQ * HID];   // tf32 bits, permuted
__device__ unsigned g_xtf [(size_t)BATCH * SEQ * INP];   // x as tf32 bits, permuted
__device__ unsigned g_wtf [GATE4 * HID];                 // W_ih as tf32 bits, permuted
__device__ unsigned g_hbuf[2 * BATCH * HID];             // ping-pong h, tf32 bits, permuted
__device__ unsigned g_cnt [NGROUP * 32];                 // counters, 128B apart

// ---------------- helpers ----------------
__device__ __forceinline__ unsigned f2tf(float f) {
    unsigned u;
    asm("cvt.rna.tf32.f32 %0, %1;" : "=r"(u) : "f"(f));
    return u;
}
__device__ __forceinline__ void mma_tf32(float d[4],
                                         unsigned a0, unsigned a1, unsigned a2, unsigned a3,
                                         unsigned b0, unsigned b1) {
    asm volatile(
        "mma.sync.aligned.m16n8k8.row.col.f32.tf32.tf32.f32 "
        "{%0,%1,%2,%3}, {%4,%5,%6,%7}, {%8,%9}, {%0,%1,%2,%3};"
        : "+f"(d[0]), "+f"(d[1]), "+f"(d[2]), "+f"(d[3])
        : "r"(a0), "r"(a1), "r"(a2), "r"(a3), "r"(b0), "r"(b1));
}
__device__ __forceinline__ float sigf(float x) { return 1.0f / (1.0f + __expf(-x)); }
__device__ __forceinline__ float tanh_fast(float x) { return 2.0f * sigf(2.0f * x) - 1.0f; }
__device__ __forceinline__ int pquad(int i) {      // permuted pos within 16-word block
    return 4 * ((i & 7) >> 1) + 2 * (i >> 3) + (i & 1);
}
__device__ __forceinline__ void cp_async16(unsigned dst_smem, const void* src) {
    asm volatile("cp.async.cg.shared.global [%0], [%1], 16;"
                 :: "r"(dst_smem), "l"(src) : "memory");
}
__device__ __forceinline__ void cp_commit() { asm volatile("cp.async.commit_group;" ::: "memory"); }
__device__ __forceinline__ void cp_wait0()  { asm volatile("cp.async.wait_group 0;" ::: "memory"); }
__device__ __forceinline__ void cp_wait1()  { asm volatile("cp.async.wait_group 1;" ::: "memory"); }

__device__ __forceinline__ void red_add_release(unsigned* p) {
    asm volatile("red.global.add.release.gpu.u32 [%0], %1;" :: "l"(p), "r"(1u) : "memory");
}
__device__ __forceinline__ unsigned ld_acquire(const unsigned* p) {
    unsigned v;
    asm volatile("ld.global.acquire.gpu.u32 %0, [%1];" : "=r"(v) : "l"(p) : "memory");
    return v;
}

__global__ void reset_sync_kernel() {
    if (threadIdx.x < NGROUP * 32) g_cnt[threadIdx.x] = 0u;
}

// ---------------------------------------------------------------------------
// K-1: convert fp32 -> tf32 bits with quad permutation along K (row-major).
// ---------------------------------------------------------------------------
__global__ void __launch_bounds__(256) convert_tf_kernel(
    const float* __restrict__ src, unsigned* __restrict__ dst, int K, long total)
{
    for (long i = (long)blockIdx.x * blockDim.x + threadIdx.x; i < total;
         i += (long)gridDim.x * blockDim.x) {
        long row = i / K;
        int  k   = (int)(i - row * K);
        int  pk  = (k & ~15) + pquad(k & 15);
        dst[row * K + pk] = f2tf(src[i]);
    }
}

// ---------------------------------------------------------------------------
// K1 v4: C[M,1024] = A[M,K] @ W[1024,K]^T + (bih+bhh)   (tf32 bits in, fp32 out)
// CTA 128x64, BK=32, 8 warps = 4(m)x2(n), warp tile 32x32.
// cp.async 16B chunks into padded SMEM (stride 48 = 16 mod 32).
// ---------------------------------------------------------------------------
#define AST  48
#define TBUF (192 * AST)
#define GEMM_SMEM (2 * TBUF * 4)       // 73728 bytes

__global__ void __launch_bounds__(256, 2) gemm_xg_kernel(
    const unsigned* __restrict__ A, const unsigned* __restrict__ W,
    const float* __restrict__ bih, const float* __restrict__ bhh,
    float* __restrict__ C, int K)
{
    extern __shared__ unsigned gsm[];

    const int tid  = threadIdx.x;
    const int lane = tid & 31;
    const int warp = tid >> 5;
    const int wm   = (warp >> 1) * 32;      // 4 m-warps
    const int wn   = (warp & 1) * 32;       // 2 n-warps
    const int  n0  = blockIdx.x * 64;       // n fast-varying (W reuse in L2)
    const long m0  = (long)blockIdx.y * 128;

    auto issueTile = [&](int buf, int k0) {
        unsigned sb = (unsigned)__cvta_generic_to_shared(gsm + buf * TBUF);
        #pragma unroll
        for (int i = 0; i < 4; i++) {                     // A: 128 rows x 8 chunks
            int q = tid + 256 * i, row = q >> 3, ch = q & 7;
            cp_async16(sb + (row * AST + ch * 4) * 4,
                       A + (m0 + row) * (long)K + k0 + ch * 4);
        }
        #pragma unroll
        for (int i = 0; i < 2; i++) {                     // B: 64 rows x 8 chunks
            int q = tid + 256 * i, row = q >> 3, ch = q & 7;
            cp_async16(sb + ((128 + row) * AST + ch * 4) * 4,
                       W + (long)(n0 + row) * K + k0 + ch * 4);
        }
        cp_commit();
    };

    float d[2][4][4] = {};
    const int gp  = lane >> 2;
    const int tg  = lane & 3;
    const int tg2 = tg * 2;

    auto compute = [&](int buf) {
        const unsigned* Ab = gsm + buf * TBUF;
        const unsigned* Bb = Ab + 128 * AST;
        #pragma unroll
        for (int m = 0; m < 2; m++) {
            const int kb = m * 16 + 4 * tg;
            uint4 a[2][2];
            #pragma unroll
            for (int r = 0; r < 2; r++) {
                a[r][0] = *reinterpret_cast<const uint4*>(&Ab[(wm + 16 * r + gp    ) * AST + kb]);
                a[r][1] = *reinterpret_cast<const uint4*>(&Ab[(wm + 16 * r + gp + 8) * AST + kb]);
            }
            #pragma unroll
            for (int j = 0; j < 4; j++) {
                uint4 b = *reinterpret_cast<const uint4*>(&Bb[(wn + 8 * j + gp) * AST + kb]);
                #pragma unroll
                for (int r = 0; r < 2; r++) {
                    mma_tf32(d[r][j], a[r][0].x, a[r][1].x, a[r][0].y, a[r][1].y, b.x, b.y);
                    mma_tf32(d[r][j], a[r][0].z, a[r][1].z, a[r][0].w, a[r][1].w, b.z, b.w);
                }
            }
        }
    };

    issueTile(0, 0);
    int cur = 0;
    for (int k0 = 0; k0 < K; k0 += 32) {
        const bool more = (k0 + 32) < K;
        if (more) { issueTile(cur ^ 1, k0 + 32); cp_wait1(); } else { cp_wait0(); }
        __syncthreads();
        compute(cur);
        __syncthreads();
        cur ^= 1;
    }

    #pragma unroll
    for (int r = 0; r < 2; r++) {
        const int row = wm + 16 * r + gp;
        #pragma unroll
        for (int j = 0; j < 4; j++) {
            int c = n0 + wn + 8 * j + tg2;
            float bi0 = bih[c] + bhh[c];
            float bi1 = bih[c + 1] + bhh[c + 1];
            C[(m0 + row    ) * GATE4 + c    ] = d[r][j][0] + bi0;
            C[(m0 + row    ) * GATE4 + c + 1] = d[r][j][1] + bi1;
            C[(m0 + row + 8) * GATE4 + c    ] = d[r][j][2] + bi0;
            C[(m0 + row + 8) * GATE4 + c + 1] = d[r][j][3] + bi1;
        }
    }
}

// ---------------------------------------------------------------------------
// K2: persistent LSTM layer. 128 CTAs = 16 batch-groups x 8 slices.
// W fragments in registers; h (permuted tf32 bits) reloaded via cp.async.cg,
// 4 x 16B per thread = full 16 rows x 256 words.
// ---------------------------------------------------------------------------
#define WSTR 272   // 272 % 32 == 16 -> conflict-free LDS.128
#define GSTR 132
#define SMEM_REC ((GROWS * WSTR + GROWS * GSTR + GROWS * JCOLS) * 4)

__device__ __forceinline__ void group_arrive(int group) {
    __syncthreads();
    if (threadIdx.x == 0) red_add_release(&g_cnt[group * 32]);
}
__device__ __forceinline__ void group_wait(int group, unsigned target) {
    if (threadIdx.x == 0) {
        while ((int)(ld_acquire(&g_cnt[group * 32]) - target) < 0) { }
    }
    __syncthreads();
}

__global__ void __launch_bounds__(256, 1) lstm_layer_kernel(
    const float* __restrict__ xg, const float* __restrict__ Whh,
    unsigned* __restrict__ hseq, unsigned* __restrict__ hbuf, int store_all)
{
    extern __shared__ unsigned smem[];
    unsigned* Hs = smem;                          // [16][WSTR] h_prev (tf32, permuted)
    float*    Gs = (float*)(smem + GROWS * WSTR); // [16][GSTR] gate pre-acts
    float*    Cs = Gs + GROWS * GSTR;             // [16*32]    cell state

    const int tid   = threadIdx.x;
    const int lane  = tid & 31;
    const int warp  = tid >> 5;
    const int group = blockIdx.x >> 3;
    const int slice = blockIdx.x & 7;
    const int b0    = group * GROWS;
    const int j0    = slice * JCOLS;
    const int wn    = warp * 16;
    const int gp    = lane >> 2;
    const int tg    = lane & 3;
    const int tg2   = tg * 2;

    // ---- load W fragments into registers (once; step-invariant) ----
    uint4 wreg[16][2];
    #pragma unroll
    for (int m = 0; m < 16; m++) {
        #pragma unroll
        for (int nf = 0; nf < 2; nf++) {
            int rl = wn + nf * 8 + gp;
            int gr = (rl >> 5) * 256 + j0 + (rl & 31);
            const float* wp = Whh + gr * 256 + 16 * m;
            float2 lo = *reinterpret_cast<const float2*>(wp + 2 * tg);      // kf even
            float2 hi = *reinterpret_cast<const float2*>(wp + 8 + 2 * tg);  // kf odd
            wreg[m][nf] = make_uint4(f2tf(lo.x), f2tf(lo.y), f2tf(hi.x), f2tf(hi.y));
        }
    }

    // zero cell state + our slice of hbuf buffer 0 (zeros: permutation moot)
    for (int e = tid; e < GROWS * JCOLS; e += 256) {
        Cs[e] = 0.0f;
        int bl = e >> 5, j = e & 31;
        hbuf[(b0 + bl) * HID + j0 + j] = 0u;
    }
    group_arrive(group);

    const int ebl0 = tid >> 5;            // 0..7
    const int ej   = tid & 31;
    const int ejp  = (ej & ~15) + pquad(ej & 15);   // permuted column offset

    // cp.async reload mapping: FOUR 16B chunks per thread (full 16x256 words)
    const unsigned sH = (unsigned)__cvta_generic_to_shared(Hs);

    for (int t = 0; t < SEQ; t++) {
        const unsigned* hsrc = hbuf + (t & 1) * (BATCH * HID);
        unsigned*       hdst = hbuf + ((t + 1) & 1) * (BATCH * HID);

        // prefetch xg for this step (independent of the barrier)
        float xr[8];
        #pragma unroll
        for (int rr = 0; rr < 2; rr++) {
            int bl = ebl0 + rr * 8;
            long xbase = ((long)(b0 + bl) * SEQ + t) * GATE4 + j0 + ej;
            xr[rr * 4 + 0] = __ldg(&xg[xbase      ]);
            xr[rr * 4 + 1] = __ldg(&xg[xbase + 256]);
            xr[rr * 4 + 2] = __ldg(&xg[xbase + 512]);
            xr[rr * 4 + 3] = __ldg(&xg[xbase + 768]);
        }

        group_wait(group, (unsigned)(t + 1) * NSLICE);

        // reload h_prev: 4 cp.async.cg 16B per thread (L2-only, pre-permuted)
        #pragma unroll
        for (int i = 0; i < 4; i++) {
            int q = tid + 256 * i;            // 0..1023
            int row = q >> 6;                 // 0..15
            int ch  = q & 63;                 // 0..63 (16B chunks per row)
            cp_async16(sH + (row * WSTR + ch * 4) * 4,
                       hsrc + (b0 + row) * HID + ch * 4);
        }
        cp_commit();
        cp_wait0();
        __syncthreads();

        float d[2][4] = {}, e2[2][4] = {};
        #pragma unroll
        for (int m = 0; m < 16; m++) {
            const int kb = m * 16 + 4 * tg;
            uint4 va = *reinterpret_cast<const uint4*>(&Hs[ gp      * WSTR + kb]);
            uint4 vb = *reinterpret_cast<const uint4*>(&Hs[(gp + 8) * WSTR + kb]);
            #pragma unroll
            for (int nf = 0; nf < 2; nf++) {
                mma_tf32(d[nf],  va.x, vb.x, va.y, vb.y, wreg[m][nf].x, wreg[m][nf].y);
                mma_tf32(e2[nf], va.z, vb.z, va.w, vb.w, wreg[m][nf].z, wreg[m][nf].w);
            }
        }

        // stage gate pre-activations (sum the split accumulators here)
        #pragma unroll
        for (int nf = 0; nf < 2; nf++) {
            int c = wn + nf * 8 + tg2;
            Gs[ gp      * GSTR + c    ] = d[nf][0] + e2[nf][0];
            Gs[ gp      * GSTR + c + 1] = d[nf][1] + e2[nf][1];
            Gs[(gp + 8) * GSTR + c    ] = d[nf][2] + e2[nf][2];
            Gs[(gp + 8) * GSTR + c + 1] = d[nf][3] + e2[nf][3];
        }
        __syncthreads();

        // gate nonlinearity + state update: 2 (b,j) cells per thread
        #pragma unroll
        for (int rr = 0; rr < 2; rr++) {
            int bl = ebl0 + rr * 8;
            float gi = Gs[bl * GSTR +      ej] + xr[rr * 4 + 0];
            float gf = Gs[bl * GSTR + 32 + ej] + xr[rr * 4 + 1];
            float gg = Gs[bl * GSTR + 64 + ej] + xr[rr * 4 + 2];
            float go = Gs[bl * GSTR + 96 + ej] + xr[rr * 4 + 3];
            float si = sigf(gi), sf = sigf(gf), so = sigf(go);
            float cv = sf * Cs[bl * JCOLS + ej] + si * tanh_fast(gg);
            Cs[bl * JCOLS + ej] = cv;
            unsigned hb = f2tf(so * tanh_fast(cv));
            hdst[(b0 + bl) * HID + j0 + ejp] = hb;          // permuted tf32 bits
            if (store_all || t == SEQ - 1)
                hseq[((long)(b0 + bl) * SEQ + t) * HID + j0 + ejp] = hb;
        }
        group_arrive(group);
    }
}

// ---------------------------------------------------------------------------
// K3: head. out[b, :] = tanh(h_last @ W1^T + b1) @ W2^T + b2
// hseq holds permuted tf32 bits -> unpermute + cast on load.
// ---------------------------------------------------------------------------
__global__ void __launch_bounds__(128) head_kernel(
    const unsigned* __restrict__ hseq,
    const float* __restrict__ W1, const float* __restrict__ b1,
    const float* __restrict__ W2, const float* __restrict__ b2,
    float* __restrict__ out)
{
    __shared__ float hl[256];
    __shared__ float z[128];
    const int b = blockIdx.x, tid = threadIdx.x;

    for (int i = tid; i < 256; i += 128) {
        int pi = (i & ~15) + pquad(i & 15);
        hl[i] = __uint_as_float(hseq[((long)b * SEQ + (SEQ - 1)) * HID + pi]);
    }
    __syncthreads();

    {
        float acc = b1[tid];
        const float* w = W1 + tid * 256;
        #pragma unroll 8
        for (int h = 0; h < 256; h++) acc += hl[h] * w[h];
        z[tid] = tanhf(acc);
    }
    __syncthreads();

    if (tid < 96) {
        float acc = b2[tid];
        const float* w = W2 + tid * 128;
        #pragma unroll 8
        for (int l = 0; l < 128; l++) acc += z[l] * w[l];
        out[b * 96 + tid] = acc;
    }
}

// ---------------------------------------------------------------------------
extern "C" void kernel_launch(void* const* d_in, const int* in_sizes, int n_in,
                              void* d_out, int out_size)
{
    const float* x    = (const float*)d_in[0];
    const float* Wih0 = (const float*)d_in[1];
    const float* Whh0 = (const float*)d_in[2];
    const float* bih0 = (const float*)d_in[3];
    const float* bhh0 = (const float*)d_in[4];
    const float* Wih1 = (const float*)d_in[5];
    const float* Whh1 = (const float*)d_in[6];
    const float* bih1 = (const float*)d_in[7];
    const float* bhh1 = (const float*)d_in[8];
    const float* W1   = (const float*)d_in[9];
    const float* b1   = (const float*)d_in[10];
    const float* W2   = (const float*)d_in[11];
    const float* b2   = (const float*)d_in[12];
    float* out = (float*)d_out;

    float *xg; unsigned *hseq, *xtf, *wtf, *hbuf;
    cudaGetSymbolAddress((void**)&xg,   g_xg);
    cudaGetSymbolAddress((void**)&hseq, g_hseq);
    cudaGetSymbolAddress((void**)&xtf,  g_xtf);
    cudaGetSymbolAddress((void**)&wtf,  g_wtf);
    cudaGetSymbolAddress((void**)&hbuf, g_hbuf);

    cudaFuncSetAttribute((const void*)lstm_layer_kernel,
                         cudaFuncAttributeMaxDynamicSharedMemorySize, SMEM_REC);
    cudaFuncSetAttribute((const void*)gemm_xg_kernel,
                         cudaFuncAttributeMaxDynamicSharedMemorySize, GEMM_SMEM);

    dim3 gg(GATE4 / 64, (BATCH * SEQ) / 128);

    // pre-convert x and W_ih0 (tf32 bits, quad-permuted along K)
    convert_tf_kernel<<<512, 256>>>(x, xtf, INP, (long)BATCH * SEQ * INP);
    convert_tf_kernel<<<64, 256>>>(Wih0, wtf, INP, (long)GATE4 * INP);

    // layer 0
    gemm_xg_kernel<<<gg, 256, GEMM_SMEM>>>(xtf, wtf, bih0, bhh0, xg, INP);
    reset_sync_kernel<<<1, NGROUP * 32>>>();
    lstm_layer_kernel<<<NGROUP * NSLICE, 256, SMEM_REC>>>(xg, Whh0, hseq, hbuf, 1);

    // layer 1 (A = hseq already tf32-permuted; convert W_ih1)
    convert_tf_kernel<<<256, 256>>>(Wih1, wtf, HID, (long)GATE4 * HID);
    gemm_xg_kernel<<<gg, 256, GEMM_SMEM>>>(hseq, wtf, bih1, bhh1, xg, HID);
    reset_sync_kernel<<<1, NGROUP * 32>>>();
    lstm_layer_kernel<<<NGROUP * NSLICE, 256, SMEM_REC>>>(xg, Whh1, hseq, hbuf, 0);

    // head
    head_kernel<<<BATCH, 128>>>(hseq, W1, b1, W2, b2, out);
}